// round 11
// baseline (speedup 1.0000x reference)
#include <cuda_runtime.h>
#include <cfloat>

// ---------------------------------------------------------------------------
// PillarMaxPooling: h = relu((x @ W) * bn_scale + bn_shift); segment_max -> M
//   k1: counting-bucket scatter of point IDS (int4-vectorized)
//   k2: warp-per-pillar, 3-stage pipeline across pillars (R7). FEATURE-PAIR
//       f32x2 mainloop: SMEM rows are plain 48B-padded row-major; x-pairs come
//       from LDS.128; weight pairs (w2k,w2k+1) live in 20 regs. Low register
//       count -> 4 CTA/SM (one wave at grid 592) to saturate the L1 pipe.
// ---------------------------------------------------------------------------

#define CAP      64
#define MAXM     262144
#define OVFCAP   65536
#define BN_EPS   1e-3f
#define K2_THREADS 256
#define K2_WARPS   8
#define K2_GRID  592            // 4 CTAs/SM x 148 SMs: exactly one wave
#define ROWW     12             // SMEM row stride in floats (48B, 16B-aligned)

__device__ int   d_count[MAXM];                 // zero-init, k2 re-zeroes
__device__ int   d_bucket[(size_t)MAXM * CAP];
__device__ int   d_ovflist[OVFCAP];
__device__ int   d_ovfcnt;                      // zero-init

typedef unsigned long long u64;

__device__ __forceinline__ u64 pk2(float x, float y) {
    u64 r; asm("mov.b64 %0, {%1, %2};" : "=l"(r) : "f"(x), "f"(y)); return r;
}
__device__ __forceinline__ void upk2(u64 v, float& x, float& y) {
    asm("mov.b64 {%0, %1}, %2;" : "=f"(x), "=f"(y) : "l"(v));
}
__device__ __forceinline__ u64 fma2(u64 a, u64 b, u64 c) {
    u64 d; asm("fma.rn.f32x2 %0, %1, %2, %3;" : "=l"(d) : "l"(a), "l"(b), "l"(c)); return d;
}
__device__ __forceinline__ u64 mul2(u64 a, u64 b) {
    u64 d; asm("mul.rn.f32x2 %0, %1, %2;" : "=l"(d) : "l"(a), "l"(b)); return d;
}

__device__ __forceinline__ void put_point(int i, int p) {
    int s = atomicAdd(&d_count[i], 1);
    if (s < CAP) {
        d_bucket[(unsigned)i * CAP + s] = p;
    } else {
        int o = atomicAdd(&d_ovfcnt, 1);
        if (o < OVFCAP) d_ovflist[o] = p;
        else atomicSub(&d_ovfcnt, 1);
    }
}

__global__ void k1_scatter(const int* __restrict__ idx, int P) {
    int t  = blockIdx.x * blockDim.x + threadIdx.x;
    int p0 = t * 4;
    if (p0 + 3 < P) {
        int4 v = *reinterpret_cast<const int4*>(idx + p0);
        put_point(v.x, p0);
        put_point(v.y, p0 + 1);
        put_point(v.z, p0 + 2);
        put_point(v.w, p0 + 3);
    } else {
        for (int p = p0; p < P; p++) put_point(idx[p], p);
    }
}

// Feature-pair mainloop over row-major padded SMEM rows.
// Per point: 3 LDS.128 -> 6 u64 feature pairs (last partially garbage, weight
// pairs beyond k=9 are zero), 10 fma2 across 2 channel chains, 2 FADD, 2 max.
__device__ __forceinline__ void fp_mainloop(const float* buf, int m,
                                            const u64* wA, const u64* wB,
                                            float& mA, float& mB) {
#pragma unroll 2
    for (int j = 0; j < m; j++) {
        const ulonglong2* q = reinterpret_cast<const ulonglong2*>(buf + j * ROWW);
        ulonglong2 q0 = q[0], q1 = q[1], q2 = q[2];
        u64 a = mul2(q0.x, wA[0]);
        u64 b = mul2(q0.x, wB[0]);
        a = fma2(q0.y, wA[1], a);  b = fma2(q0.y, wB[1], b);
        a = fma2(q1.x, wA[2], a);  b = fma2(q1.x, wB[2], b);
        a = fma2(q1.y, wA[3], a);  b = fma2(q1.y, wB[3], b);
        a = fma2(q2.x, wA[4], a);  b = fma2(q2.x, wB[4], b);
        float ae, ao, be, bo;
        upk2(a, ae, ao);
        upk2(b, be, bo);
        mA = fmaxf(mA, ae + ao);
        mB = fmaxf(mB, be + bo);
    }
}

__global__ void __launch_bounds__(K2_THREADS, 4)
k2_compute(const float* __restrict__ gf, const float* __restrict__ W,
           const float* __restrict__ gamma, const float* __restrict__ beta,
           const float* __restrict__ mean,  const float* __restrict__ var,
           const int* __restrict__ idx, float* __restrict__ out, int M) {
    __shared__ __align__(16) float sm[K2_WARPS][2][32 * ROWW];   // 24 KB

    int lane = threadIdx.x & 31;
    int wloc = threadIdx.x >> 5;

    int gwarp = (blockIdx.x * K2_THREADS + threadIdx.x) >> 5;
    int nw    = (gridDim.x * K2_THREADS) >> 5;

    int cA = 2 * lane, cB = 2 * lane + 1;
    float sA = gamma[cA] * rsqrtf(var[cA] + BN_EPS);
    float sB = gamma[cB] * rsqrtf(var[cB] + BN_EPS);
    float bA = beta[cA] - mean[cA] * sA;
    float bB = beta[cB] - mean[cB] * sB;

    // weight FEATURE pairs: wA[kk] = (W[2kk][cA], W[2kk+1][cA]) * sA
    u64 wA[5], wB[5];
#pragma unroll
    for (int kk = 0; kk < 5; kk++) {
        wA[kk] = pk2(W[(2 * kk) * 64 + cA] * sA, W[(2 * kk + 1) * 64 + cA] * sA);
        wB[kk] = pk2(W[(2 * kk) * 64 + cB] * sB, W[(2 * kk + 1) * 64 + cB] * sB);
    }

    // ---- pipeline prologue -------------------------------------------------
    int i0 = gwarp, i1 = i0 + nw, i2 = i1 + nw, i3 = i2 + nw;

    int n0 = (i0 < M) ? d_count[i0] : 0;
    int m0 = n0 < 32 ? n0 : 32;
    float2 r0, r1, r2, r3, r4;
    if (i0 < M && lane < m0) {
        int pid = d_bucket[(unsigned)i0 * CAP + lane];
        const float2* row = reinterpret_cast<const float2*>(gf + (unsigned)pid * 10u);
        r0 = row[0]; r1 = row[1]; r2 = row[2]; r3 = row[3]; r4 = row[4];
    }
    int n1  = (i1 < M) ? d_count[i1] : 0;
    int id1 = 0;
    if (i1 < M && lane < (n1 < 32 ? n1 : 32)) id1 = d_bucket[(unsigned)i1 * CAP + lane];
    int n2  = (i2 < M) ? d_count[i2] : 0;

    int cur = 0;
    // ---- pipelined main loop ------------------------------------------------
    while (i0 < M) {
        float* buf = sm[wloc][cur];

        // stage 1: deposit rows(i0) into row-major padded SMEM
        if (lane < m0) {
            float* s = buf + lane * ROWW;
            *reinterpret_cast<float2*>(s)     = r0;
            *reinterpret_cast<float2*>(s + 2) = r1;
            *reinterpret_cast<float2*>(s + 4) = r2;
            *reinterpret_cast<float2*>(s + 6) = r3;
            *reinterpret_cast<float2*>(s + 8) = r4;
        }
        // stage 2: issue rows(i1) LDGs (uses id1 from last iteration)
        int m1 = n1 < 32 ? n1 : 32;
        if (i1 < M && lane < m1) {
            const float2* row = reinterpret_cast<const float2*>(gf + (unsigned)id1 * 10u);
            r0 = row[0]; r1 = row[1]; r2 = row[2]; r3 = row[3]; r4 = row[4];
        }
        // stage 3: issue ids(i2) LDG
        int id2 = 0;
        if (i2 < M && lane < (n2 < 32 ? n2 : 32)) id2 = d_bucket[(unsigned)i2 * CAP + lane];
        // stage 4: issue count(i3) LDG
        int n3 = (i3 < M) ? d_count[i3] : 0;

        __syncwarp();

        // compute pillar i0
        float mA = -FLT_MAX, mB = -FLT_MAX;
        fp_mainloop(buf, m0, wA, wB, mA, mB);

        // rare: extra chunks (32 < n <= CAP)
        if (n0 > 32) {
            int nc = n0 < CAP ? n0 : CAP;
            for (int base = 32; base < nc; base += 32) {
                int m = nc - base; if (m > 32) m = 32;
                __syncwarp();
                if (lane < m) {
                    int pid = d_bucket[(unsigned)i0 * CAP + base + lane];
                    const float2* row = reinterpret_cast<const float2*>(gf + (unsigned)pid * 10u);
                    float* s = buf + lane * ROWW;
                    *reinterpret_cast<float2*>(s)     = row[0];
                    *reinterpret_cast<float2*>(s + 2) = row[1];
                    *reinterpret_cast<float2*>(s + 4) = row[2];
                    *reinterpret_cast<float2*>(s + 6) = row[3];
                    *reinterpret_cast<float2*>(s + 8) = row[4];
                }
                __syncwarp();
                fp_mainloop(buf, m, wA, wB, mA, mB);
            }
        }
        // rare: overflow (n > CAP)
        if (n0 > CAP) {
            int V = d_ovfcnt; if (V > OVFCAP) V = OVFCAP;
            int mine = 0;
            for (int e = 0; e < V; e++) {
                int pid = d_ovflist[e];
                if (idx[pid] == i0) {
                    mine++;
                    float xa = 0.f, ya = 0.f;
#pragma unroll
                    for (int kk = 0; kk < 5; kk++) {
                        float f0 = gf[(unsigned)pid * 10u + 2 * kk];
                        float f1 = gf[(unsigned)pid * 10u + 2 * kk + 1];
                        float wa0, wa1, wb0, wb1;
                        upk2(wA[kk], wa0, wa1);
                        upk2(wB[kk], wb0, wb1);
                        xa = fmaf(f0, wa0, fmaf(f1, wa1, xa));
                        ya = fmaf(f0, wb0, fmaf(f1, wb1, ya));
                    }
                    mA = fmaxf(mA, xa);
                    mB = fmaxf(mB, ya);
                }
            }
            if (lane == 0 && mine) atomicSub(&d_ovfcnt, mine);
        }

        if (lane == 0 && n0 > 0) d_count[i0] = 0;   // self-reset for graph replay

        float o0 = 0.0f, o1 = 0.0f;
        if (n0 > 0) {
            o0 = fmaxf(mA + bA, 0.0f);
            o1 = fmaxf(mB + bB, 0.0f);
        }
        *reinterpret_cast<float2*>(out + (unsigned)i0 * 64 + cA) = make_float2(o0, o1);

        // pipeline shift
        i0 = i1; n0 = n1; m0 = m1;
        i1 = i2; n1 = n2; id1 = id2;
        i2 = i3; n2 = n3;
        i3 += nw;
        cur ^= 1;
    }
}

extern "C" void kernel_launch(void* const* d_in, const int* in_sizes, int n_in,
                              void* d_out, int out_size) {
    const float* gf    = (const float*)d_in[0];
    const int*   idx   = (const int*)  d_in[1];
    const float* W     = (const float*)d_in[3];
    const float* gamma = (const float*)d_in[4];
    const float* beta  = (const float*)d_in[5];
    const float* mean  = (const float*)d_in[6];
    const float* var   = (const float*)d_in[7];
    float*       out   = (float*)d_out;

    int P = in_sizes[1];
    int M = out_size / 64;

    int g1 = (P / 4 + 255) / 256 + 1;
    k1_scatter<<<g1, 256>>>(idx, P);
    k2_compute<<<K2_GRID, K2_THREADS>>>(gf, W, gamma, beta, mean, var, idx, out, M);
}